// round 1
// baseline (speedup 1.0000x reference)
#include <cuda_runtime.h>
#include <cuda_bf16.h>
#include <cstdint>

// Problem constants (fixed by the dataset)
#define Bc 16
#define Nc 256
#define Dc 128
#define Lc 3
#define Ec 32768
#define BN (Bc*Nc)          // 4096
#define ADJ_ELEMS (Bc*Nc*Nc)  // 1,048,576

// ---------------- scratch (device globals; no allocation allowed) ----------
__device__ float g_adj[ADJ_ELEMS];     // 4 MB
__device__ float g_h  [BN*Dc];
__device__ float g_ht [BN*Dc];
__device__ float g_hs [BN*Dc];
__device__ float g_agg[BN*Dc];
__device__ float g_p  [BN*Dc];
__device__ float g_q  [BN*Dc];
__device__ float g_e1 [Ec*Dc];         // 16 MB

__device__ __forceinline__ float silu_f(float y) {
    // y * sigmoid(y) = y / (1 + exp(-y)); approx div+exp are ~1e-6 accurate
    return __fdividef(y, 1.0f + __expf(-y));
}

// ---------------- adj build ------------------------------------------------
__global__ void zero_kernel(float* __restrict__ p, int n) {
    int i = blockIdx.x * blockDim.x + threadIdx.x;
    int stride = gridDim.x * blockDim.x;
    for (; i < n; i += stride) p[i] = 0.0f;
}

__global__ void scatter_adj_kernel(const int* __restrict__ ei,
                                   const float* __restrict__ ea,
                                   float* __restrict__ adj) {
    int e = blockIdx.x * blockDim.x + threadIdx.x;
    if (e >= Ec) return;
    int u = ei[e];          // eb*N + src
    int v = ei[Ec + e];     // eb*N + dst
    int b = u >> 8;         // N = 256
    int s = u & 255;
    int d = v & 255;
    float w = ea[e];
    // reference: adj[b,s,d] += w, then adj += adj^T  ==> symmetric add
    atomicAdd(&adj[(b << 16) + (s << 8) + d], w);
    atomicAdd(&adj[(b << 16) + (d << 8) + s], w);
}

// ---------------- encoder: h = x * encW + encb -----------------------------
__global__ void encode_kernel(const float* __restrict__ x,
                              const float* __restrict__ encW,
                              const float* __restrict__ encb,
                              float* __restrict__ h) {
    int i = blockIdx.x;           // node row
    int d = threadIdx.x;          // 128 threads
    h[i * Dc + d] = fmaf(x[i], encW[d], encb[d]);
}

// ---------------- dual GEMM: O1 = X@W1 + b1, O2 = X@W2 ---------------------
// X: [BN,128], W: [128,128] row-major
__global__ void __launch_bounds__(128) dual_mm_kernel(
        const float* __restrict__ X,
        const float* __restrict__ W1,
        const float* __restrict__ W2,
        const float* __restrict__ b1,
        float* __restrict__ O1, float* __restrict__ O2) {
    __shared__ float xr[Dc];
    int i = blockIdx.x;
    int d = threadIdx.x;
    xr[d] = X[i * Dc + d];
    __syncthreads();
    float a1 = b1[d];
    float a2 = 0.0f;
#pragma unroll 8
    for (int k = 0; k < Dc; k++) {
        float xv = xr[k];
        a1 = fmaf(xv, W1[k * Dc + d], a1);
        a2 = fmaf(xv, W2[k * Dc + d], a2);
    }
    O1[i * Dc + d] = a1;
    O2[i * Dc + d] = a2;
}

// ---------------- message + LN + silu + masked aggregate -------------------
// One warp handles one (b,i); 8 warps/block share the hs[b] stream (L1 reuse).
// Lane owns d = lane*4 .. lane*4+3.
__global__ void __launch_bounds__(256) msg_kernel(
        const float* __restrict__ ht,   // already includes msg_b
        const float* __restrict__ hs,
        const float* __restrict__ adj,
        const float* __restrict__ wjv,  // msg_W[l, 2D, :]
        const float* __restrict__ g,
        const float* __restrict__ be,
        float* __restrict__ agg) {
    int warp = threadIdx.x >> 5;
    int lane = threadIdx.x & 31;
    int b = blockIdx.x >> 5;                  // 32 blocks per batch
    int i = ((blockIdx.x & 31) << 3) + warp;  // 8 i per block
    int node = b * Nc + i;
    int d4 = lane << 2;

    const float4 HT = *(const float4*)(ht + node * Dc + d4);
    const float4 WJ = *(const float4*)(wjv + d4);
    const float4 G  = *(const float4*)(g + d4);
    const float4 BE = *(const float4*)(be + d4);
    const float* hsb  = hs + b * Nc * Dc;
    const float* arow = adj + node * Nc;

    float ax = 0.f, ay = 0.f, az = 0.f, aw = 0.f;

#pragma unroll 2
    for (int j = 0; j < Nc; j++) {
        float a = __ldg(arow + j);
        float4 s = *(const float4*)(hsb + j * Dc + d4);
        float p0 = fmaf(a, WJ.x, HT.x + s.x);
        float p1 = fmaf(a, WJ.y, HT.y + s.y);
        float p2 = fmaf(a, WJ.z, HT.z + s.z);
        float p3 = fmaf(a, WJ.w, HT.w + s.w);
        float sm = (p0 + p1) + (p2 + p3);
        float sq = fmaf(p0, p0, fmaf(p1, p1, fmaf(p2, p2, p3 * p3)));
#pragma unroll
        for (int o = 16; o; o >>= 1) {
            sm += __shfl_xor_sync(0xffffffffu, sm, o);
            sq += __shfl_xor_sync(0xffffffffu, sq, o);
        }
        float mu  = sm * (1.0f / 128.0f);
        float var = fmaf(sq, 1.0f / 128.0f, -mu * mu);
        float r   = rsqrtf(var + 1e-5f);
        if (j != i) {
            float t, y;
            t = (p0 - mu) * r; y = fmaf(t, G.x, BE.x); ax += silu_f(y);
            t = (p1 - mu) * r; y = fmaf(t, G.y, BE.y); ay += silu_f(y);
            t = (p2 - mu) * r; y = fmaf(t, G.z, BE.z); az += silu_f(y);
            t = (p3 - mu) * r; y = fmaf(t, G.w, BE.w); aw += silu_f(y);
        }
    }
    float4 o4 = make_float4(ax, ay, az, aw);
    *(float4*)(agg + node * Dc + d4) = o4;
}

// ---------------- update: h += silu(LN(concat(h,agg)@Wu + bu)) -------------
__global__ void __launch_bounds__(128) update_kernel(
        float* __restrict__ h,
        const float* __restrict__ agg,
        const float* __restrict__ Wu,   // [256,128]
        const float* __restrict__ bu,
        const float* __restrict__ g,
        const float* __restrict__ be) {
    __shared__ float cat[2 * Dc];
    __shared__ float rs[4], rq[4];
    int i = blockIdx.x;
    int d = threadIdx.x;
    int warp = d >> 5, lane = d & 31;
    cat[d]      = h[i * Dc + d];
    cat[Dc + d] = agg[i * Dc + d];
    __syncthreads();
    float a = bu[d];
#pragma unroll 8
    for (int k = 0; k < 2 * Dc; k++)
        a = fmaf(cat[k], Wu[k * Dc + d], a);
    // LN over 128 threads
    float s = a, q = a * a;
#pragma unroll
    for (int o = 16; o; o >>= 1) {
        s += __shfl_xor_sync(0xffffffffu, s, o);
        q += __shfl_xor_sync(0xffffffffu, q, o);
    }
    if (lane == 0) { rs[warp] = s; rq[warp] = q; }
    __syncthreads();
    s = rs[0] + rs[1] + rs[2] + rs[3];
    q = rq[0] + rq[1] + rq[2] + rq[3];
    float mu  = s * (1.0f / 128.0f);
    float var = fmaf(q, 1.0f / 128.0f, -mu * mu);
    float r   = rsqrtf(var + 1e-5f);
    float y   = fmaf((a - mu) * r, g[d], be[d]);
    h[i * Dc + d] = cat[d] + silu_f(y);
}

// ---------------- decoder stage 1: e1 = silu(p[u]+q[v]+ea*w1c) -------------
__global__ void __launch_bounds__(128) edge1_kernel(
        const float* __restrict__ p, const float* __restrict__ q,
        const int* __restrict__ ei, const float* __restrict__ ea,
        const float* __restrict__ w1c, float* __restrict__ e1) {
    int e = blockIdx.x;
    int d = threadIdx.x;
    int u = ei[e];
    int v = ei[Ec + e];
    float a = ea[e];
    float y = p[u * Dc + d] + q[v * Dc + d] + a * w1c[d];
    e1[e * Dc + d] = silu_f(y);
}

// ---------------- decoder stage 2: out = tanh(silu(e1@W2+b2)@w3+b3) --------
__global__ void __launch_bounds__(256) edge2_kernel(
        const float* __restrict__ e1,
        const float* __restrict__ W2,   // [128,64]
        const float* __restrict__ b2,
        const float* __restrict__ w3,   // [64,1]
        const float* __restrict__ b3,
        float* __restrict__ out) {
    __shared__ float W2s[Dc * 64];
    __shared__ float w3s[64];
    __shared__ float b2s[64];
    for (int t = threadIdx.x; t < Dc * 64; t += 256) W2s[t] = W2[t];
    if (threadIdx.x < 64) {
        w3s[threadIdx.x] = w3[threadIdx.x];
        b2s[threadIdx.x] = b2[threadIdx.x];
    }
    __syncthreads();
    float b3v = b3[0];
    int warp = threadIdx.x >> 5, lane = threadIdx.x & 31;
    int gw = blockIdx.x * 8 + warp;
    int nW = gridDim.x * 8;
    for (int e = gw; e < Ec; e += nW) {
        const float* er = e1 + e * Dc;
        float a0 = b2s[lane], a1 = b2s[lane + 32];
#pragma unroll 8
        for (int k = 0; k < Dc; k++) {
            float s = er[k];                         // broadcast load
            a0 = fmaf(s, W2s[k * 64 + lane], a0);
            a1 = fmaf(s, W2s[k * 64 + lane + 32], a1);
        }
        a0 = silu_f(a0);
        a1 = silu_f(a1);
        float t = fmaf(a0, w3s[lane], a1 * w3s[lane + 32]);
#pragma unroll
        for (int o = 16; o; o >>= 1) t += __shfl_xor_sync(0xffffffffu, t, o);
        if (lane == 0) out[e] = tanhf(t + b3v);
    }
}

// ---------------- launch ---------------------------------------------------
extern "C" void kernel_launch(void* const* d_in, const int* in_sizes, int n_in,
                              void* d_out, int out_size) {
    const float* x     = (const float*)d_in[0];
    const int*   ei    = (const int*)  d_in[1];
    const float* ea    = (const float*)d_in[2];
    // d_in[3] = batch (derivable, unused)
    const float* encW  = (const float*)d_in[4];
    const float* encb  = (const float*)d_in[5];
    const float* msgW  = (const float*)d_in[6];   // [L,257,128]
    const float* msgb  = (const float*)d_in[7];   // [L,128]
    const float* msgg  = (const float*)d_in[8];
    const float* msgbe = (const float*)d_in[9];
    const float* updW  = (const float*)d_in[10];  // [L,256,128]
    const float* updb  = (const float*)d_in[11];
    const float* updg  = (const float*)d_in[12];
    const float* updbe = (const float*)d_in[13];
    const float* decW1 = (const float*)d_in[14];  // [257,128]
    const float* decb1 = (const float*)d_in[15];
    const float* decW2 = (const float*)d_in[16];  // [128,64]
    const float* decb2 = (const float*)d_in[17];
    const float* decW3 = (const float*)d_in[18];  // [64,1]
    const float* decb3 = (const float*)d_in[19];
    float* out = (float*)d_out;

    float *adj, *h, *ht, *hs, *agg, *p, *q, *e1;
    cudaGetSymbolAddress((void**)&adj, g_adj);
    cudaGetSymbolAddress((void**)&h,   g_h);
    cudaGetSymbolAddress((void**)&ht,  g_ht);
    cudaGetSymbolAddress((void**)&hs,  g_hs);
    cudaGetSymbolAddress((void**)&agg, g_agg);
    cudaGetSymbolAddress((void**)&p,   g_p);
    cudaGetSymbolAddress((void**)&q,   g_q);
    cudaGetSymbolAddress((void**)&e1,  g_e1);

    zero_kernel<<<1024, 256>>>(adj, ADJ_ELEMS);
    scatter_adj_kernel<<<(Ec + 255) / 256, 256>>>(ei, ea, adj);
    encode_kernel<<<BN, Dc>>>(x, encW, encb, h);

    for (int l = 0; l < Lc; l++) {
        const float* Wl = msgW + (size_t)l * 257 * Dc;
        dual_mm_kernel<<<BN, Dc>>>(h, Wl, Wl + Dc * Dc, msgb + l * Dc, ht, hs);
        msg_kernel<<<Bc * 32, 256>>>(ht, hs, adj, Wl + 2 * Dc * Dc,
                                     msgg + l * Dc, msgbe + l * Dc, agg);
        update_kernel<<<BN, Dc>>>(h, agg, updW + (size_t)l * 2 * Dc * Dc,
                                  updb + l * Dc, updg + l * Dc, updbe + l * Dc);
    }

    dual_mm_kernel<<<BN, Dc>>>(h, decW1, decW1 + Dc * Dc, decb1, p, q);
    edge1_kernel<<<Ec, Dc>>>(p, q, ei, ea, decW1 + 2 * Dc * Dc, e1);
    edge2_kernel<<<512, 256>>>(e1, decW2, decb2, decW3, decb3, out);
}

// round 2
// speedup vs baseline: 1.4083x; 1.4083x over previous
#include <cuda_runtime.h>
#include <cstdint>

// Problem constants
#define Bc 16
#define Nc 256
#define Dc 128
#define Lc 3
#define Ec 32768
#define BN (Bc*Nc)            // 4096
#define ADJ_ELEMS (Bc*Nc*Nc)  // 1,048,576

typedef unsigned long long u64;

// ---------------- scratch ---------------------------------------------------
__device__ float  g_adj[ADJ_ELEMS];   // 4 MB
__device__ float  g_h  [BN*Dc];
__device__ float  g_ht [BN*Dc];
__device__ float  g_hs [BN*Dc];
__device__ float  g_agg[BN*Dc];
__device__ float  g_p  [BN*Dc];
__device__ float  g_q  [BN*Dc];
__device__ float  g_e1 [Ec*Dc];       // 16 MB
__device__ float  g_C  [BN*Nc];       // 4 MB   C[i,j] = ht_i . hs_j
__device__ float2 g_mr [BN*Nc];       // 8 MB   {r, mu*r} per pair
__device__ float4 g_statT[BN];        // {Sht/128, Qht, 2*Tht, 0}
__device__ float4 g_statS[BN];        // {Shs/128, Qhs, 2*Ths, 0}
__device__ float  g_wstat[2];         // {Swj/128, Qwj}

// ---------------- helpers ---------------------------------------------------
__device__ __forceinline__ float silu_f(float y) {
    return __fdividef(y, 1.0f + __expf(-y));
}
__device__ __forceinline__ float tanh_ap(float x) {
    float r; asm("tanh.approx.f32 %0,%1;" : "=f"(r) : "f"(x)); return r;
}
__device__ __forceinline__ u64 pk2(float lo, float hi) {
    u64 r; asm("mov.b64 %0,{%1,%2};" : "=l"(r) : "f"(lo), "f"(hi)); return r;
}
__device__ __forceinline__ void upk2(u64 v, float& lo, float& hi) {
    asm("mov.b64 {%0,%1},%2;" : "=f"(lo), "=f"(hi) : "l"(v));
}
__device__ __forceinline__ u64 fma2v(u64 a, u64 b, u64 c) {
    u64 d; asm("fma.rn.f32x2 %0,%1,%2,%3;" : "=l"(d) : "l"(a), "l"(b), "l"(c)); return d;
}
__device__ __forceinline__ u64 add2v(u64 a, u64 b) {
    u64 d; asm("add.rn.f32x2 %0,%1,%2;" : "=l"(d) : "l"(a), "l"(b)); return d;
}
__device__ __forceinline__ u64 mul2v(u64 a, u64 b) {
    u64 d; asm("mul.rn.f32x2 %0,%1,%2;" : "=l"(d) : "l"(a), "l"(b)); return d;
}

// ---------------- adj build -------------------------------------------------
__global__ void zero_kernel(float* __restrict__ p, int n) {
    int i = blockIdx.x * blockDim.x + threadIdx.x;
    int stride = gridDim.x * blockDim.x;
    for (; i < n; i += stride) p[i] = 0.0f;
}

__global__ void scatter_adj_kernel(const int* __restrict__ ei,
                                   const float* __restrict__ ea,
                                   float* __restrict__ adj) {
    int e = blockIdx.x * blockDim.x + threadIdx.x;
    if (e >= Ec) return;
    int u = ei[e];
    int v = ei[Ec + e];
    int b = u >> 8;
    int s = u & 255;
    int d = v & 255;
    float w = ea[e];
    atomicAdd(&adj[(b << 16) + (s << 8) + d], w);
    atomicAdd(&adj[(b << 16) + (d << 8) + s], w);
}

__global__ void encode_kernel(const float* __restrict__ x,
                              const float* __restrict__ encW,
                              const float* __restrict__ encb,
                              float* __restrict__ h) {
    int i = blockIdx.x;
    int d = threadIdx.x;
    h[i * Dc + d] = fmaf(x[i], encW[d], encb[d]);
}

// ---------------- dual GEMM (16 rows/block, register blocked) ---------------
__global__ void __launch_bounds__(128) dual_mm_kernel(
        const float* __restrict__ X,
        const float* __restrict__ W1,
        const float* __restrict__ W2,
        const float* __restrict__ b1,
        float* __restrict__ O1, float* __restrict__ O2) {
    __shared__ float xs[16][Dc];
    int base = blockIdx.x * 16;
    int t = threadIdx.x;
#pragma unroll
    for (int r = 0; r < 16; r++) xs[r][t] = X[(base + r) * Dc + t];
    __syncthreads();
    float bv = b1[t];
    float a1[16], a2[16];
#pragma unroll
    for (int r = 0; r < 16; r++) { a1[r] = bv; a2[r] = 0.0f; }
    for (int k4 = 0; k4 < 32; k4++) {
        float w1k[4], w2k[4];
#pragma unroll
        for (int kk = 0; kk < 4; kk++) {
            w1k[kk] = W1[(k4 * 4 + kk) * Dc + t];
            w2k[kk] = W2[(k4 * 4 + kk) * Dc + t];
        }
#pragma unroll
        for (int r = 0; r < 16; r++) {
            float4 x4 = *(float4*)&xs[r][k4 * 4];
            a1[r] = fmaf(x4.x, w1k[0], a1[r]);
            a1[r] = fmaf(x4.y, w1k[1], a1[r]);
            a1[r] = fmaf(x4.z, w1k[2], a1[r]);
            a1[r] = fmaf(x4.w, w1k[3], a1[r]);
            a2[r] = fmaf(x4.x, w2k[0], a2[r]);
            a2[r] = fmaf(x4.y, w2k[1], a2[r]);
            a2[r] = fmaf(x4.z, w2k[2], a2[r]);
            a2[r] = fmaf(x4.w, w2k[3], a2[r]);
        }
    }
#pragma unroll
    for (int r = 0; r < 16; r++) {
        O1[(base + r) * Dc + t] = a1[r];
        O2[(base + r) * Dc + t] = a2[r];
    }
}

// ---------------- C[i,j] = ht_i . hs_j (batched, 16 i-rows/block) -----------
__global__ void __launch_bounds__(256) cdot_kernel(
        const float* __restrict__ ht,
        const float* __restrict__ hs,
        float* __restrict__ C) {
    __shared__ float xs[16][Dc];
    int base = blockIdx.x * 16;            // node base of the 16 i-rows
    int t = threadIdx.x;                   // j = t
    // cooperative load of 16 ht rows
#pragma unroll
    for (int c = 0; c < 8; c++) {
        int idx = c * 256 + t;
        xs[idx >> 7][idx & 127] = ht[base * Dc + idx];
    }
    __syncthreads();
    const float* hsr = hs + (((base >> 8) << 8) + t) * Dc;   // hs row j of this batch
    float acc[16];
#pragma unroll
    for (int r = 0; r < 16; r++) acc[r] = 0.0f;
    for (int k4 = 0; k4 < 32; k4++) {
        float4 h4 = *(const float4*)(hsr + k4 * 4);
#pragma unroll
        for (int r = 0; r < 16; r++) {
            float4 x4 = *(float4*)&xs[r][k4 * 4];
            acc[r] = fmaf(x4.x, h4.x, acc[r]);
            acc[r] = fmaf(x4.y, h4.y, acc[r]);
            acc[r] = fmaf(x4.z, h4.z, acc[r]);
            acc[r] = fmaf(x4.w, h4.w, acc[r]);
        }
    }
#pragma unroll
    for (int r = 0; r < 16; r++) C[(base + r) * Nc + t] = acc[r];
}

// ---------------- per-node stats (for LN factorization) ---------------------
__global__ void __launch_bounds__(128) nstats_kernel(
        const float* __restrict__ ht,
        const float* __restrict__ hs,
        const float* __restrict__ wj,
        float4* __restrict__ statT,
        float4* __restrict__ statS,
        float* __restrict__ wstat) {
    __shared__ float red[4][8];
    int node = blockIdx.x;
    int d = threadIdx.x;
    int warp = d >> 5, lane = d & 31;
    float tv = ht[node * Dc + d];
    float sv = hs[node * Dc + d];
    float wv = wj[d];
    float v[8] = { tv, tv * tv, tv * wv, sv, sv * sv, sv * wv, wv, wv * wv };
#pragma unroll
    for (int q = 0; q < 8; q++) {
        float s = v[q];
#pragma unroll
        for (int o = 16; o; o >>= 1) s += __shfl_xor_sync(0xffffffffu, s, o);
        if (lane == 0) red[warp][q] = s;
    }
    __syncthreads();
    if (d == 0) {
        float s[8];
#pragma unroll
        for (int q = 0; q < 8; q++)
            s[q] = red[0][q] + red[1][q] + red[2][q] + red[3][q];
        statT[node] = make_float4(s[0] * (1.0f / 128.0f), s[1], 2.0f * s[2], 0.0f);
        statS[node] = make_float4(s[3] * (1.0f / 128.0f), s[4], 2.0f * s[5], 0.0f);
        if (node == 0) { wstat[0] = s[6] * (1.0f / 128.0f); wstat[1] = s[7]; }
    }
}

// ---------------- per-pair LN stats: mu, rsqrt ------------------------------
__global__ void __launch_bounds__(256) pstats_kernel(
        const float4* __restrict__ statT,
        const float4* __restrict__ statS,
        const float* __restrict__ adj,
        const float* __restrict__ C,
        const float* __restrict__ wstat,
        float2* __restrict__ mr) {
    int node = blockIdx.x;
    int j = threadIdx.x;
    float4 T = statT[node];
    float4 S = statS[((node >> 8) << 8) + j];
    float a = adj[node * Nc + j];
    float c = C[node * Nc + j];
    float Sw = wstat[0], Qw = wstat[1];
    float mu   = fmaf(a, Sw, T.x + S.x);
    float t1   = T.z + S.z;
    float base = fmaf(2.0f, c, T.y + S.y);
    float sq   = fmaf(a, fmaf(a, Qw, t1), base);
    float var  = fmaf(sq, 1.0f / 128.0f, -mu * mu);
    float r    = rsqrtf(var + 1e-5f);
    mr[node * Nc + j] = make_float2(r, mu * r);
}

// ---------------- message: silu(LN(pre)) masked-sum over j ------------------
// warp per (b,i); lane owns d = lane*4..+3; packed f32x2 math, tanh silu.
__global__ void __launch_bounds__(256) msg_kernel(
        const float* __restrict__ ht,
        const float* __restrict__ hs,
        const float* __restrict__ adj,
        const float* __restrict__ wjv,
        const float* __restrict__ g,
        const float* __restrict__ be,
        const float2* __restrict__ mr,
        float* __restrict__ agg) {
    int warp = threadIdx.x >> 5;
    int lane = threadIdx.x & 31;
    int b = blockIdx.x >> 5;
    int i = ((blockIdx.x & 31) << 3) + warp;
    int node = b * Nc + i;
    int d4 = lane << 2;

    const ulonglong2 HT = *(const ulonglong2*)(ht + node * Dc + d4);
    const ulonglong2 WJ = *(const ulonglong2*)(wjv + d4);
    float4 G4 = *(const float4*)(g + d4);
    float4 B4 = *(const float4*)(be + d4);
    u64 Gh01 = pk2(0.5f * G4.x, 0.5f * G4.y);
    u64 Gh23 = pk2(0.5f * G4.z, 0.5f * G4.w);
    u64 Bh01 = pk2(0.5f * B4.x, 0.5f * B4.y);
    u64 Bh23 = pk2(0.5f * B4.z, 0.5f * B4.w);

    const float* hsb = hs + b * Nc * Dc;
    const float* arow = adj + node * Nc;
    const float2* mrow = mr + node * Nc;

    u64 aP0 = 0, aP1 = 0, aT0 = 0, aT1 = 0;

#pragma unroll 2
    for (int j = 0; j < Nc; j++) {
        float a = __ldg(arow + j);
        float2 m = __ldg(mrow + j);              // {r, mu*r}
        ulonglong2 sv = *(const ulonglong2*)(hsb + j * Dc + d4);
        u64 a2  = pk2(a, a);
        u64 r2  = pk2(m.x, m.x);
        u64 nm  = pk2(-m.y, -m.y);
        u64 rg0 = mul2v(r2, Gh01);
        u64 rg1 = mul2v(r2, Gh23);
        u64 c0  = fma2v(nm, Gh01, Bh01);
        u64 c1  = fma2v(nm, Gh23, Bh23);
        u64 p0  = fma2v(a2, WJ.x, add2v(HT.x, sv.x));
        u64 p1  = fma2v(a2, WJ.y, add2v(HT.y, sv.y));
        u64 y0  = fma2v(p0, rg0, c0);            // y2 = 0.5 * LN-out
        u64 y1  = fma2v(p1, rg1, c1);
        float f0, f1, f2, f3;
        upk2(y0, f0, f1); upk2(y1, f2, f3);
        u64 t0 = pk2(tanh_ap(f0), tanh_ap(f1));
        u64 t1 = pk2(tanh_ap(f2), tanh_ap(f3));
        aP0 = add2v(aP0, y0);  aP1 = add2v(aP1, y1);   // silu = y2 + y2*tanh(y2)
        aT0 = fma2v(y0, t0, aT0);
        aT1 = fma2v(y1, t1, aT1);
    }

    float ax, ay, az, aw;
    upk2(add2v(aP0, aT0), ax, ay);
    upk2(add2v(aP1, aT1), az, aw);

    // subtract diagonal j == i (exactly the loop's arithmetic, scalar)
    {
        float a = arow[i];
        float2 m = mrow[i];
        const float4 s = *(const float4*)(hsb + i * Dc + d4);
        float h0, h1, h2, h3, w0, w1, w2, w3, g0, g1, g2, g3, e0, e1, e2, e3;
        upk2(HT.x, h0, h1); upk2(HT.y, h2, h3);
        upk2(WJ.x, w0, w1); upk2(WJ.y, w2, w3);
        upk2(Gh01, g0, g1); upk2(Gh23, g2, g3);
        upk2(Bh01, e0, e1); upk2(Bh23, e2, e3);
        float r = m.x, nmur = -m.y;
        float p, y2;
        p = fmaf(a, w0, h0 + s.x); y2 = fmaf(p, r * g0, fmaf(nmur, g0, e0)); ax -= fmaf(y2, tanh_ap(y2), y2);
        p = fmaf(a, w1, h1 + s.y); y2 = fmaf(p, r * g1, fmaf(nmur, g1, e1)); ay -= fmaf(y2, tanh_ap(y2), y2);
        p = fmaf(a, w2, h2 + s.z); y2 = fmaf(p, r * g2, fmaf(nmur, g2, e2)); az -= fmaf(y2, tanh_ap(y2), y2);
        p = fmaf(a, w3, h3 + s.w); y2 = fmaf(p, r * g3, fmaf(nmur, g3, e3)); aw -= fmaf(y2, tanh_ap(y2), y2);
    }
    *(float4*)(agg + node * Dc + d4) = make_float4(ax, ay, az, aw);
}

// ---------------- update: h += silu(LN(concat(h,agg)@Wu + bu)) --------------
__global__ void __launch_bounds__(128) update_kernel(
        float* __restrict__ h,
        const float* __restrict__ agg,
        const float* __restrict__ Wu,
        const float* __restrict__ bu,
        const float* __restrict__ g,
        const float* __restrict__ be) {
    __shared__ float cat[16][2 * Dc];
    __shared__ float ubuf[16][132];
    int base = blockIdx.x * 16;
    int t = threadIdx.x;
    int warp = t >> 5, lane = t & 31;
#pragma unroll
    for (int r = 0; r < 16; r++) {
        cat[r][t]      = h[(base + r) * Dc + t];
        cat[r][Dc + t] = agg[(base + r) * Dc + t];
    }
    __syncthreads();
    float bv = bu[t];
    float acc[16];
#pragma unroll
    for (int r = 0; r < 16; r++) acc[r] = bv;
    for (int k4 = 0; k4 < 64; k4++) {
        float wk[4];
#pragma unroll
        for (int kk = 0; kk < 4; kk++) wk[kk] = Wu[(k4 * 4 + kk) * Dc + t];
#pragma unroll
        for (int r = 0; r < 16; r++) {
            float4 x4 = *(float4*)&cat[r][k4 * 4];
            acc[r] = fmaf(x4.x, wk[0], acc[r]);
            acc[r] = fmaf(x4.y, wk[1], acc[r]);
            acc[r] = fmaf(x4.z, wk[2], acc[r]);
            acc[r] = fmaf(x4.w, wk[3], acc[r]);
        }
    }
#pragma unroll
    for (int r = 0; r < 16; r++) ubuf[r][t] = acc[r];
    __syncthreads();
    // LN + silu + residual: warp w handles rows 4w..4w+3
#pragma unroll
    for (int rr = 0; rr < 4; rr++) {
        int r = warp * 4 + rr;
        float4 u4 = *(float4*)&ubuf[r][lane * 4];
        float s = (u4.x + u4.y) + (u4.z + u4.w);
        float q = fmaf(u4.x, u4.x, fmaf(u4.y, u4.y, fmaf(u4.z, u4.z, u4.w * u4.w)));
#pragma unroll
        for (int o = 16; o; o >>= 1) {
            s += __shfl_xor_sync(0xffffffffu, s, o);
            q += __shfl_xor_sync(0xffffffffu, q, o);
        }
        float mu  = s * (1.0f / 128.0f);
        float var = fmaf(q, 1.0f / 128.0f, -mu * mu);
        float rv  = rsqrtf(var + 1e-5f);
        float4 g4  = *(const float4*)(g + lane * 4);
        float4 be4 = *(const float4*)(be + lane * 4);
        float4 c4  = *(float4*)&cat[r][lane * 4];
        float4 o4;
        o4.x = c4.x + silu_f(fmaf((u4.x - mu) * rv, g4.x, be4.x));
        o4.y = c4.y + silu_f(fmaf((u4.y - mu) * rv, g4.y, be4.y));
        o4.z = c4.z + silu_f(fmaf((u4.z - mu) * rv, g4.z, be4.z));
        o4.w = c4.w + silu_f(fmaf((u4.w - mu) * rv, g4.w, be4.w));
        *(float4*)(h + (base + r) * Dc + lane * 4) = o4;
    }
}

// ---------------- decoder ---------------------------------------------------
__global__ void __launch_bounds__(128) edge1_kernel(
        const float* __restrict__ p, const float* __restrict__ q,
        const int* __restrict__ ei, const float* __restrict__ ea,
        const float* __restrict__ w1c, float* __restrict__ e1) {
    int e = blockIdx.x;
    int d = threadIdx.x;
    int u = ei[e];
    int v = ei[Ec + e];
    float a = ea[e];
    float y = p[u * Dc + d] + q[v * Dc + d] + a * w1c[d];
    e1[e * Dc + d] = silu_f(y);
}

__global__ void __launch_bounds__(256) edge2_kernel(
        const float* __restrict__ e1,
        const float* __restrict__ W2,
        const float* __restrict__ b2,
        const float* __restrict__ w3,
        const float* __restrict__ b3,
        float* __restrict__ out) {
    __shared__ float W2s[Dc * 64];
    __shared__ float w3s[64];
    __shared__ float b2s[64];
    for (int t = threadIdx.x; t < Dc * 64; t += 256) W2s[t] = W2[t];
    if (threadIdx.x < 64) {
        w3s[threadIdx.x] = w3[threadIdx.x];
        b2s[threadIdx.x] = b2[threadIdx.x];
    }
    __syncthreads();
    float b3v = b3[0];
    int warp = threadIdx.x >> 5, lane = threadIdx.x & 31;
    int gw = blockIdx.x * 8 + warp;
    int nW = gridDim.x * 8;
    for (int e = gw; e < Ec; e += nW) {
        const float* er = e1 + e * Dc;
        float a0 = b2s[lane], a1 = b2s[lane + 32];
#pragma unroll 8
        for (int k = 0; k < Dc; k++) {
            float s = er[k];
            a0 = fmaf(s, W2s[k * 64 + lane], a0);
            a1 = fmaf(s, W2s[k * 64 + lane + 32], a1);
        }
        a0 = silu_f(a0);
        a1 = silu_f(a1);
        float t = fmaf(a0, w3s[lane], a1 * w3s[lane + 32]);
#pragma unroll
        for (int o = 16; o; o >>= 1) t += __shfl_xor_sync(0xffffffffu, t, o);
        if (lane == 0) out[e] = tanhf(t + b3v);
    }
}

// ---------------- launch ----------------------------------------------------
extern "C" void kernel_launch(void* const* d_in, const int* in_sizes, int n_in,
                              void* d_out, int out_size) {
    const float* x     = (const float*)d_in[0];
    const int*   ei    = (const int*)  d_in[1];
    const float* ea    = (const float*)d_in[2];
    const float* encW  = (const float*)d_in[4];
    const float* encb  = (const float*)d_in[5];
    const float* msgW  = (const float*)d_in[6];
    const float* msgb  = (const float*)d_in[7];
    const float* msgg  = (const float*)d_in[8];
    const float* msgbe = (const float*)d_in[9];
    const float* updW  = (const float*)d_in[10];
    const float* updb  = (const float*)d_in[11];
    const float* updg  = (const float*)d_in[12];
    const float* updbe = (const float*)d_in[13];
    const float* decW1 = (const float*)d_in[14];
    const float* decb1 = (const float*)d_in[15];
    const float* decW2 = (const float*)d_in[16];
    const float* decb2 = (const float*)d_in[17];
    const float* decW3 = (const float*)d_in[18];
    const float* decb3 = (const float*)d_in[19];
    float* out = (float*)d_out;

    float *adj, *h, *ht, *hs, *agg, *p, *q, *e1, *C, *wst;
    float2* mr; float4 *sT, *sS;
    cudaGetSymbolAddress((void**)&adj, g_adj);
    cudaGetSymbolAddress((void**)&h,   g_h);
    cudaGetSymbolAddress((void**)&ht,  g_ht);
    cudaGetSymbolAddress((void**)&hs,  g_hs);
    cudaGetSymbolAddress((void**)&agg, g_agg);
    cudaGetSymbolAddress((void**)&p,   g_p);
    cudaGetSymbolAddress((void**)&q,   g_q);
    cudaGetSymbolAddress((void**)&e1,  g_e1);
    cudaGetSymbolAddress((void**)&C,   g_C);
    cudaGetSymbolAddress((void**)&mr,  g_mr);
    cudaGetSymbolAddress((void**)&sT,  g_statT);
    cudaGetSymbolAddress((void**)&sS,  g_statS);
    cudaGetSymbolAddress((void**)&wst, g_wstat);

    zero_kernel<<<1024, 256>>>(adj, ADJ_ELEMS);
    scatter_adj_kernel<<<(Ec + 255) / 256, 256>>>(ei, ea, adj);
    encode_kernel<<<BN, Dc>>>(x, encW, encb, h);

    for (int l = 0; l < Lc; l++) {
        const float* Wl  = msgW + (size_t)l * 257 * Dc;
        const float* wjv = Wl + 2 * Dc * Dc;
        dual_mm_kernel<<<BN / 16, 128>>>(h, Wl, Wl + Dc * Dc, msgb + l * Dc, ht, hs);
        nstats_kernel<<<BN, 128>>>(ht, hs, wjv, sT, sS, wst);
        cdot_kernel<<<BN / 16, 256>>>(ht, hs, C);
        pstats_kernel<<<BN, 256>>>(sT, sS, adj, C, wst, mr);
        msg_kernel<<<Bc * 32, 256>>>(ht, hs, adj, wjv,
                                     msgg + l * Dc, msgbe + l * Dc, mr, agg);
        update_kernel<<<BN / 16, 128>>>(h, agg, updW + (size_t)l * 2 * Dc * Dc,
                                        updb + l * Dc, updg + l * Dc, updbe + l * Dc);
    }

    dual_mm_kernel<<<BN / 16, 128>>>(h, decW1, decW1 + Dc * Dc, decb1, p, q);
    edge1_kernel<<<Ec, Dc>>>(p, q, ei, ea, decW1 + 2 * Dc * Dc, e1);
    edge2_kernel<<<512, 256>>>(e1, decW2, decb2, decW3, decb3, out);
}

// round 3
// speedup vs baseline: 1.6946x; 1.2033x over previous
#include <cuda_runtime.h>
#include <cstdint>

#define Bc 16
#define Nc 256
#define Dc 128
#define Lc 3
#define Ec 32768
#define BN (Bc*Nc)            // 4096
#define ADJ_ELEMS (Bc*Nc*Nc)  // 1,048,576

typedef unsigned long long u64;

// ---------------- scratch ---------------------------------------------------
__device__ float  g_adj[ADJ_ELEMS];   // 4 MB
__device__ float  g_h  [BN*Dc];
__device__ float  g_ht [BN*Dc];
__device__ float  g_hs [BN*Dc];
__device__ float  g_agg[BN*Dc];
__device__ float  g_p  [BN*Dc];
__device__ float  g_q  [BN*Dc];
__device__ float  g_e1 [Ec*Dc];       // 16 MB
__device__ float2 g_mr [BN*Nc];       // 8 MB   {r, -mu*r} per pair
__device__ float4 g_statT[BN];        // {Sht/128, Qht, 2*Tht, 0}
__device__ float4 g_statS[BN];        // {Shs/128, Qhs, 2*Ths, 0}
__device__ float  g_wstat[2];         // {Swj/128, Qwj}

// ---------------- helpers ---------------------------------------------------
__device__ __forceinline__ float silu_f(float y) {
    return __fdividef(y, 1.0f + __expf(-y));
}
__device__ __forceinline__ float tanh_ap(float x) {
    float r; asm("tanh.approx.f32 %0,%1;" : "=f"(r) : "f"(x)); return r;
}
__device__ __forceinline__ u64 pk2(float lo, float hi) {
    u64 r; asm("mov.b64 %0,{%1,%2};" : "=l"(r) : "f"(lo), "f"(hi)); return r;
}
__device__ __forceinline__ void upk2(u64 v, float& lo, float& hi) {
    asm("mov.b64 {%0,%1},%2;" : "=f"(lo), "=f"(hi) : "l"(v));
}
__device__ __forceinline__ u64 fma2v(u64 a, u64 b, u64 c) {
    u64 d; asm("fma.rn.f32x2 %0,%1,%2,%3;" : "=l"(d) : "l"(a), "l"(b), "l"(c)); return d;
}
__device__ __forceinline__ u64 add2v(u64 a, u64 b) {
    u64 d; asm("add.rn.f32x2 %0,%1,%2;" : "=l"(d) : "l"(a), "l"(b)); return d;
}

// ---------------- adj build -------------------------------------------------
__global__ void zero_kernel(float* __restrict__ p, int n) {
    int i = blockIdx.x * blockDim.x + threadIdx.x;
    int stride = gridDim.x * blockDim.x;
    for (; i < n; i += stride) p[i] = 0.0f;
}

__global__ void scatter_adj_kernel(const int* __restrict__ ei,
                                   const float* __restrict__ ea,
                                   float* __restrict__ adj) {
    int e = blockIdx.x * blockDim.x + threadIdx.x;
    if (e >= Ec) return;
    int u = ei[e];
    int v = ei[Ec + e];
    int b = u >> 8;
    int s = u & 255;
    int d = v & 255;
    float w = ea[e];
    atomicAdd(&adj[(b << 16) + (s << 8) + d], w);
    atomicAdd(&adj[(b << 16) + (d << 8) + s], w);
}

__global__ void encode_kernel(const float* __restrict__ x,
                              const float* __restrict__ encW,
                              const float* __restrict__ encb,
                              float* __restrict__ h) {
    int i = blockIdx.x;
    int d = threadIdx.x;
    h[i * Dc + d] = fmaf(x[i], encW[d], encb[d]);
}

// ---------------- dual GEMM (8 rows/block) ----------------------------------
__global__ void __launch_bounds__(128) dual_mm_kernel(
        const float* __restrict__ X,
        const float* __restrict__ W1,
        const float* __restrict__ W2,
        const float* __restrict__ b1,
        float* __restrict__ O1, float* __restrict__ O2) {
    __shared__ float xs[8][132];
    int base = blockIdx.x * 8;
    int t = threadIdx.x;
#pragma unroll
    for (int c = 0; c < 8; c++) {
        int idx = c * 128 + t;             // 0..1023
        xs[idx >> 7][idx & 127] = X[base * Dc + idx];
    }
    __syncthreads();
    float bv = b1[t];
    float a1[8], a2[8];
#pragma unroll
    for (int r = 0; r < 8; r++) { a1[r] = bv; a2[r] = 0.0f; }
#pragma unroll 2
    for (int k4 = 0; k4 < 32; k4++) {
        float w1k[4], w2k[4];
#pragma unroll
        for (int kk = 0; kk < 4; kk++) {
            w1k[kk] = W1[(k4 * 4 + kk) * Dc + t];
            w2k[kk] = W2[(k4 * 4 + kk) * Dc + t];
        }
#pragma unroll
        for (int r = 0; r < 8; r++) {
            float4 x4 = *(float4*)&xs[r][k4 * 4];
            a1[r] = fmaf(x4.x, w1k[0], a1[r]);
            a1[r] = fmaf(x4.y, w1k[1], a1[r]);
            a1[r] = fmaf(x4.z, w1k[2], a1[r]);
            a1[r] = fmaf(x4.w, w1k[3], a1[r]);
            a2[r] = fmaf(x4.x, w2k[0], a2[r]);
            a2[r] = fmaf(x4.y, w2k[1], a2[r]);
            a2[r] = fmaf(x4.z, w2k[2], a2[r]);
            a2[r] = fmaf(x4.w, w2k[3], a2[r]);
        }
    }
#pragma unroll
    for (int r = 0; r < 8; r++) {
        O1[(base + r) * Dc + t] = a1[r];
        O2[(base + r) * Dc + t] = a2[r];
    }
}

// ---------------- per-node stats --------------------------------------------
__global__ void __launch_bounds__(128) nstats_kernel(
        const float* __restrict__ ht,
        const float* __restrict__ hs,
        const float* __restrict__ wj,
        float4* __restrict__ statT,
        float4* __restrict__ statS,
        float* __restrict__ wstat) {
    __shared__ float red[4][8];
    int node = blockIdx.x;
    int d = threadIdx.x;
    int warp = d >> 5, lane = d & 31;
    float tv = ht[node * Dc + d];
    float sv = hs[node * Dc + d];
    float wv = wj[d];
    float v[8] = { tv, tv * tv, tv * wv, sv, sv * sv, sv * wv, wv, wv * wv };
#pragma unroll
    for (int q = 0; q < 8; q++) {
        float s = v[q];
#pragma unroll
        for (int o = 16; o; o >>= 1) s += __shfl_xor_sync(0xffffffffu, s, o);
        if (lane == 0) red[warp][q] = s;
    }
    __syncthreads();
    if (d == 0) {
        float s[8];
#pragma unroll
        for (int q = 0; q < 8; q++)
            s[q] = red[0][q] + red[1][q] + red[2][q] + red[3][q];
        statT[node] = make_float4(s[0] * (1.0f / 128.0f), s[1], 2.0f * s[2], 0.0f);
        statS[node] = make_float4(s[3] * (1.0f / 128.0f), s[4], 2.0f * s[5], 0.0f);
        if (node == 0) { wstat[0] = s[6] * (1.0f / 128.0f); wstat[1] = s[7]; }
    }
}

// ---------------- fused C=ht.hs + LN pair-stats -> mr -----------------------
// block: 16 i-rows x 64 j-cols, 256 threads; thread owns (4 i-rows, 1 j).
__global__ void __launch_bounds__(256) cdot_mr_kernel(
        const float* __restrict__ ht,
        const float* __restrict__ hs,
        const float* __restrict__ adj,
        const float4* __restrict__ statT,
        const float4* __restrict__ statS,
        const float* __restrict__ wstat,
        float2* __restrict__ mr) {
    __shared__ float hts[16][132];
    __shared__ float hss[64][132];
    __shared__ float4 sTs[16];
    int base  = blockIdx.x * 16;           // i base
    int b     = base >> 8;
    int jbase = blockIdx.y * 64;
    int t = threadIdx.x;
#pragma unroll
    for (int c = 0; c < 8; c++) {
        int idx = c * 256 + t;             // 0..2047
        hts[idx >> 7][idx & 127] = ht[base * Dc + idx];
    }
#pragma unroll
    for (int c = 0; c < 32; c++) {
        int idx = c * 256 + t;             // 0..8191
        hss[idx >> 7][idx & 127] = hs[(b * Nc + jbase) * Dc + idx];
    }
    if (t < 16) sTs[t] = statT[base + t];
    __syncthreads();

    int jl = t & 63;
    int rg = (t >> 6) * 4;                 // row group: rg..rg+3
    float acc0 = 0.f, acc1 = 0.f, acc2 = 0.f, acc3 = 0.f;
#pragma unroll 4
    for (int k4 = 0; k4 < 32; k4++) {
        float4 hv = *(float4*)&hss[jl][k4 * 4];
        float4 x0 = *(float4*)&hts[rg + 0][k4 * 4];
        float4 x1 = *(float4*)&hts[rg + 1][k4 * 4];
        float4 x2 = *(float4*)&hts[rg + 2][k4 * 4];
        float4 x3 = *(float4*)&hts[rg + 3][k4 * 4];
        acc0 = fmaf(x0.x, hv.x, acc0); acc0 = fmaf(x0.y, hv.y, acc0);
        acc0 = fmaf(x0.z, hv.z, acc0); acc0 = fmaf(x0.w, hv.w, acc0);
        acc1 = fmaf(x1.x, hv.x, acc1); acc1 = fmaf(x1.y, hv.y, acc1);
        acc1 = fmaf(x1.z, hv.z, acc1); acc1 = fmaf(x1.w, hv.w, acc1);
        acc2 = fmaf(x2.x, hv.x, acc2); acc2 = fmaf(x2.y, hv.y, acc2);
        acc2 = fmaf(x2.z, hv.z, acc2); acc2 = fmaf(x2.w, hv.w, acc2);
        acc3 = fmaf(x3.x, hv.x, acc3); acc3 = fmaf(x3.y, hv.y, acc3);
        acc3 = fmaf(x3.z, hv.z, acc3); acc3 = fmaf(x3.w, hv.w, acc3);
    }

    float4 S  = statS[b * Nc + jbase + jl];
    float Sw  = __ldg(wstat), Qw = __ldg(wstat + 1);
    float cacc[4] = {acc0, acc1, acc2, acc3};
#pragma unroll
    for (int rr = 0; rr < 4; rr++) {
        int row = base + rg + rr;
        float4 T = sTs[rg + rr];
        float a  = adj[row * Nc + jbase + jl];
        float mu   = fmaf(a, Sw, T.x + S.x);
        float sq   = fmaf(2.0f, cacc[rr], T.y + S.y);
        sq         = fmaf(a, fmaf(a, Qw, T.z + S.z), sq);
        float var  = fmaf(sq, 1.0f / 128.0f, -mu * mu);
        float r    = rsqrtf(var + 1e-5f);
        mr[row * Nc + jbase + jl] = make_float2(r, -mu * r);
    }
}

// ---------------- message: silu(LN(pre)) masked-sum over j ------------------
__global__ void __launch_bounds__(256) msg_kernel(
        const float* __restrict__ ht,
        const float* __restrict__ hs,
        const float* __restrict__ adj,
        const float* __restrict__ wjv,
        const float* __restrict__ g,
        const float* __restrict__ be,
        const float2* __restrict__ mr,
        float* __restrict__ agg) {
    int warp = threadIdx.x >> 5;
    int lane = threadIdx.x & 31;
    int b = blockIdx.x >> 5;
    int i = ((blockIdx.x & 31) << 3) + warp;
    int node = b * Nc + i;
    int d4 = lane << 2;

    const ulonglong2 HT = *(const ulonglong2*)(ht + node * Dc + d4);
    const ulonglong2 WJ = *(const ulonglong2*)(wjv + d4);
    float4 G4 = *(const float4*)(g + d4);
    float4 B4 = *(const float4*)(be + d4);
    u64 Gh01 = pk2(0.5f * G4.x, 0.5f * G4.y);
    u64 Gh23 = pk2(0.5f * G4.z, 0.5f * G4.w);
    u64 Bh01 = pk2(0.5f * B4.x, 0.5f * B4.y);
    u64 Bh23 = pk2(0.5f * B4.z, 0.5f * B4.w);

    const float* hsb = hs + b * Nc * Dc;
    const float* arow = adj + node * Nc;
    const float2* mrow = mr + node * Nc;

    u64 aP0 = 0, aP1 = 0, aT0 = 0, aT1 = 0;

#pragma unroll 2
    for (int j = 0; j < Nc; j++) {
        float a = __ldg(arow + j);
        float2 m = __ldg(mrow + j);              // {r, -mu*r}
        ulonglong2 sv = *(const ulonglong2*)(hsb + j * Dc + d4);
        u64 a2  = pk2(a, a);
        u64 r2  = pk2(m.x, m.x);
        u64 nm2 = pk2(m.y, m.y);
        u64 p0  = fma2v(a2, WJ.x, add2v(HT.x, sv.x));
        u64 p1  = fma2v(a2, WJ.y, add2v(HT.y, sv.y));
        u64 z0  = fma2v(p0, r2, nm2);            // (p-mu)*r
        u64 z1  = fma2v(p1, r2, nm2);
        u64 y0  = fma2v(z0, Gh01, Bh01);         // 0.5 * LN-out
        u64 y1  = fma2v(z1, Gh23, Bh23);
        float f0, f1, f2, f3;
        upk2(y0, f0, f1); upk2(y1, f2, f3);
        u64 t0 = pk2(tanh_ap(f0), tanh_ap(f1));
        u64 t1 = pk2(tanh_ap(f2), tanh_ap(f3));
        aP0 = add2v(aP0, y0);  aP1 = add2v(aP1, y1);   // silu = y2 + y2*tanh(y2)
        aT0 = fma2v(y0, t0, aT0);
        aT1 = fma2v(y1, t1, aT1);
    }

    float ax, ay, az, aw;
    upk2(add2v(aP0, aT0), ax, ay);
    upk2(add2v(aP1, aT1), az, aw);

    // subtract diagonal j == i
    {
        float a = arow[i];
        float2 m = mrow[i];
        const float4 s = *(const float4*)(hsb + i * Dc + d4);
        float h0, h1, h2, h3, w0, w1, w2, w3, g0, g1, g2, g3, e0, e1, e2, e3;
        upk2(HT.x, h0, h1); upk2(HT.y, h2, h3);
        upk2(WJ.x, w0, w1); upk2(WJ.y, w2, w3);
        upk2(Gh01, g0, g1); upk2(Gh23, g2, g3);
        upk2(Bh01, e0, e1); upk2(Bh23, e2, e3);
        float r = m.x, nmr = m.y;
        float p, z, y2;
        p = fmaf(a, w0, h0 + s.x); z = fmaf(p, r, nmr); y2 = fmaf(z, g0, e0); ax -= fmaf(y2, tanh_ap(y2), y2);
        p = fmaf(a, w1, h1 + s.y); z = fmaf(p, r, nmr); y2 = fmaf(z, g1, e1); ay -= fmaf(y2, tanh_ap(y2), y2);
        p = fmaf(a, w2, h2 + s.z); z = fmaf(p, r, nmr); y2 = fmaf(z, g2, e2); az -= fmaf(y2, tanh_ap(y2), y2);
        p = fmaf(a, w3, h3 + s.w); z = fmaf(p, r, nmr); y2 = fmaf(z, g3, e3); aw -= fmaf(y2, tanh_ap(y2), y2);
    }
    *(float4*)(agg + node * Dc + d4) = make_float4(ax, ay, az, aw);
}

// ---------------- update: h += silu(LN(concat(h,agg)@Wu + bu)) --------------
__global__ void __launch_bounds__(128) update_kernel(
        float* __restrict__ h,
        const float* __restrict__ agg,
        const float* __restrict__ Wu,
        const float* __restrict__ bu,
        const float* __restrict__ g,
        const float* __restrict__ be) {
    __shared__ float cat[8][260];
    __shared__ float ubuf[8][132];
    int base = blockIdx.x * 8;
    int t = threadIdx.x;
    int warp = t >> 5, lane = t & 31;
#pragma unroll
    for (int r = 0; r < 8; r++) {
        cat[r][t]      = h[(base + r) * Dc + t];
        cat[r][Dc + t] = agg[(base + r) * Dc + t];
    }
    __syncthreads();
    float bv = bu[t];
    float acc[8];
#pragma unroll
    for (int r = 0; r < 8; r++) acc[r] = bv;
#pragma unroll 2
    for (int k4 = 0; k4 < 64; k4++) {
        float wk[4];
#pragma unroll
        for (int kk = 0; kk < 4; kk++) wk[kk] = Wu[(k4 * 4 + kk) * Dc + t];
#pragma unroll
        for (int r = 0; r < 8; r++) {
            float4 x4 = *(float4*)&cat[r][k4 * 4];
            acc[r] = fmaf(x4.x, wk[0], acc[r]);
            acc[r] = fmaf(x4.y, wk[1], acc[r]);
            acc[r] = fmaf(x4.z, wk[2], acc[r]);
            acc[r] = fmaf(x4.w, wk[3], acc[r]);
        }
    }
#pragma unroll
    for (int r = 0; r < 8; r++) ubuf[r][t] = acc[r];
    __syncthreads();
    // warp w handles rows 2w, 2w+1
#pragma unroll
    for (int rr = 0; rr < 2; rr++) {
        int r = warp * 2 + rr;
        float4 u4 = *(float4*)&ubuf[r][lane * 4];
        float s = (u4.x + u4.y) + (u4.z + u4.w);
        float q = fmaf(u4.x, u4.x, fmaf(u4.y, u4.y, fmaf(u4.z, u4.z, u4.w * u4.w)));
#pragma unroll
        for (int o = 16; o; o >>= 1) {
            s += __shfl_xor_sync(0xffffffffu, s, o);
            q += __shfl_xor_sync(0xffffffffu, q, o);
        }
        float mu  = s * (1.0f / 128.0f);
        float var = fmaf(q, 1.0f / 128.0f, -mu * mu);
        float rv  = rsqrtf(var + 1e-5f);
        float4 g4  = *(const float4*)(g + lane * 4);
        float4 be4 = *(const float4*)(be + lane * 4);
        float4 c4  = *(float4*)&cat[r][lane * 4];
        float4 o4;
        o4.x = c4.x + silu_f(fmaf((u4.x - mu) * rv, g4.x, be4.x));
        o4.y = c4.y + silu_f(fmaf((u4.y - mu) * rv, g4.y, be4.y));
        o4.z = c4.z + silu_f(fmaf((u4.z - mu) * rv, g4.z, be4.z));
        o4.w = c4.w + silu_f(fmaf((u4.w - mu) * rv, g4.w, be4.w));
        *(float4*)(h + (base + r) * Dc + lane * 4) = o4;
    }
}

// ---------------- decoder ---------------------------------------------------
__global__ void __launch_bounds__(128) edge1_kernel(
        const float* __restrict__ p, const float* __restrict__ q,
        const int* __restrict__ ei, const float* __restrict__ ea,
        const float* __restrict__ w1c, float* __restrict__ e1) {
    int e = blockIdx.x;
    int d = threadIdx.x;
    int u = ei[e];
    int v = ei[Ec + e];
    float a = ea[e];
    float y = p[u * Dc + d] + q[v * Dc + d] + a * w1c[d];
    e1[e * Dc + d] = silu_f(y);
}

__global__ void __launch_bounds__(256) edge2_kernel(
        const float* __restrict__ e1,
        const float* __restrict__ W2,
        const float* __restrict__ b2,
        const float* __restrict__ w3,
        const float* __restrict__ b3,
        float* __restrict__ out) {
    __shared__ float W2s[Dc * 64];
    __shared__ float w3s[64];
    __shared__ float b2s[64];
    for (int t = threadIdx.x; t < Dc * 64; t += 256) W2s[t] = W2[t];
    if (threadIdx.x < 64) {
        w3s[threadIdx.x] = w3[threadIdx.x];
        b2s[threadIdx.x] = b2[threadIdx.x];
    }
    __syncthreads();
    float b3v = b3[0];
    int warp = threadIdx.x >> 5, lane = threadIdx.x & 31;
    int gw = blockIdx.x * 8 + warp;
    int nW = gridDim.x * 8;
    for (int e = gw; e < Ec; e += nW) {
        const float* er = e1 + e * Dc;
        float a0 = b2s[lane], a1 = b2s[lane + 32];
#pragma unroll 8
        for (int k4 = 0; k4 < 32; k4++) {
            float4 s4 = *(const float4*)(er + k4 * 4);
            a0 = fmaf(s4.x, W2s[(k4 * 4 + 0) * 64 + lane], a0);
            a1 = fmaf(s4.x, W2s[(k4 * 4 + 0) * 64 + lane + 32], a1);
            a0 = fmaf(s4.y, W2s[(k4 * 4 + 1) * 64 + lane], a0);
            a1 = fmaf(s4.y, W2s[(k4 * 4 + 1) * 64 + lane + 32], a1);
            a0 = fmaf(s4.z, W2s[(k4 * 4 + 2) * 64 + lane], a0);
            a1 = fmaf(s4.z, W2s[(k4 * 4 + 2) * 64 + lane + 32], a1);
            a0 = fmaf(s4.w, W2s[(k4 * 4 + 3) * 64 + lane], a0);
            a1 = fmaf(s4.w, W2s[(k4 * 4 + 3) * 64 + lane + 32], a1);
        }
        a0 = silu_f(a0);
        a1 = silu_f(a1);
        float t = fmaf(a0, w3s[lane], a1 * w3s[lane + 32]);
#pragma unroll
        for (int o = 16; o; o >>= 1) t += __shfl_xor_sync(0xffffffffu, t, o);
        if (lane == 0) out[e] = tanhf(t + b3v);
    }
}

// ---------------- launch ----------------------------------------------------
extern "C" void kernel_launch(void* const* d_in, const int* in_sizes, int n_in,
                              void* d_out, int out_size) {
    const float* x     = (const float*)d_in[0];
    const int*   ei    = (const int*)  d_in[1];
    const float* ea    = (const float*)d_in[2];
    const float* encW  = (const float*)d_in[4];
    const float* encb  = (const float*)d_in[5];
    const float* msgW  = (const float*)d_in[6];
    const float* msgb  = (const float*)d_in[7];
    const float* msgg  = (const float*)d_in[8];
    const float* msgbe = (const float*)d_in[9];
    const float* updW  = (const float*)d_in[10];
    const float* updb  = (const float*)d_in[11];
    const float* updg  = (const float*)d_in[12];
    const float* updbe = (const float*)d_in[13];
    const float* decW1 = (const float*)d_in[14];
    const float* decb1 = (const float*)d_in[15];
    const float* decW2 = (const float*)d_in[16];
    const float* decb2 = (const float*)d_in[17];
    const float* decW3 = (const float*)d_in[18];
    const float* decb3 = (const float*)d_in[19];
    float* out = (float*)d_out;

    float *adj, *h, *ht, *hs, *agg, *p, *q, *e1, *wst;
    float2* mr; float4 *sT, *sS;
    cudaGetSymbolAddress((void**)&adj, g_adj);
    cudaGetSymbolAddress((void**)&h,   g_h);
    cudaGetSymbolAddress((void**)&ht,  g_ht);
    cudaGetSymbolAddress((void**)&hs,  g_hs);
    cudaGetSymbolAddress((void**)&agg, g_agg);
    cudaGetSymbolAddress((void**)&p,   g_p);
    cudaGetSymbolAddress((void**)&q,   g_q);
    cudaGetSymbolAddress((void**)&e1,  g_e1);
    cudaGetSymbolAddress((void**)&mr,  g_mr);
    cudaGetSymbolAddress((void**)&sT,  g_statT);
    cudaGetSymbolAddress((void**)&sS,  g_statS);
    cudaGetSymbolAddress((void**)&wst, g_wstat);

    zero_kernel<<<1024, 256>>>(adj, ADJ_ELEMS);
    scatter_adj_kernel<<<(Ec + 255) / 256, 256>>>(ei, ea, adj);
    encode_kernel<<<BN, Dc>>>(x, encW, encb, h);

    for (int l = 0; l < Lc; l++) {
        const float* Wl  = msgW + (size_t)l * 257 * Dc;
        const float* wjv = Wl + 2 * Dc * Dc;
        dual_mm_kernel<<<BN / 8, 128>>>(h, Wl, Wl + Dc * Dc, msgb + l * Dc, ht, hs);
        nstats_kernel<<<BN, 128>>>(ht, hs, wjv, sT, sS, wst);
        cdot_mr_kernel<<<dim3(BN / 16, Nc / 64), 256>>>(ht, hs, adj, sT, sS, wst, mr);
        msg_kernel<<<Bc * 32, 256>>>(ht, hs, adj, wjv,
                                     msgg + l * Dc, msgbe + l * Dc, mr, agg);
        update_kernel<<<BN / 8, 128>>>(h, agg, updW + (size_t)l * 2 * Dc * Dc,
                                       updb + l * Dc, updg + l * Dc, updbe + l * Dc);
    }

    dual_mm_kernel<<<BN / 8, 128>>>(h, decW1, decW1 + Dc * Dc, decb1, p, q);
    edge1_kernel<<<Ec, Dc>>>(p, q, ei, ea, decW1 + 2 * Dc * Dc, e1);
    edge2_kernel<<<512, 256>>>(e1, decW2, decb2, decW3, decb3, out);
}

// round 5
// speedup vs baseline: 1.8328x; 1.0815x over previous
#include <cuda_runtime.h>
#include <cstdint>

#define Bc 16
#define Nc 256
#define Dc 128
#define Lc 3
#define Ec 32768
#define BN (Bc*Nc)            // 4096
#define ADJ_ELEMS (Bc*Nc*Nc)  // 1,048,576

typedef unsigned long long u64;

// ---------------- scratch ---------------------------------------------------
__device__ float  g_adj[ADJ_ELEMS];   // 4 MB
__device__ float  g_h  [BN*Dc];
__device__ float  g_ht [BN*Dc];
__device__ float  g_hs [BN*Dc];
__device__ float  g_agg[BN*Dc];
__device__ float  g_p  [BN*Dc];
__device__ float  g_q  [BN*Dc];
__device__ float2 g_mr [BN*Nc];       // 8 MB   {r, -mu*r} per pair
__device__ float4 g_statT[BN];        // {S/128, Q, 2*T, 0}
__device__ float4 g_statS[BN];
__device__ float  g_wstat[2*Lc];      // per layer {Swj/128, Qwj}

// ---------------- helpers ---------------------------------------------------
__device__ __forceinline__ float silu_f(float y) {
    return __fdividef(y, 1.0f + __expf(-y));
}
__device__ __forceinline__ float tanh_ap(float x) {
    float r; asm("tanh.approx.f32 %0,%1;" : "=f"(r) : "f"(x)); return r;
}
__device__ __forceinline__ u64 pk2(float lo, float hi) {
    u64 r; asm("mov.b64 %0,{%1,%2};" : "=l"(r) : "f"(lo), "f"(hi)); return r;
}
__device__ __forceinline__ void upk2(u64 v, float& lo, float& hi) {
    asm("mov.b64 {%0,%1},%2;" : "=f"(lo), "=f"(hi) : "l"(v));
}
__device__ __forceinline__ u64 fma2v(u64 a, u64 b, u64 c) {
    u64 d; asm("fma.rn.f32x2 %0,%1,%2,%3;" : "=l"(d) : "l"(a), "l"(b), "l"(c)); return d;
}
__device__ __forceinline__ u64 add2v(u64 a, u64 b) {
    u64 d; asm("add.rn.f32x2 %0,%1,%2;" : "=l"(d) : "l"(a), "l"(b)); return d;
}

// ---------------- adj build -------------------------------------------------
__global__ void zero_kernel(float* __restrict__ p, int n) {
    int i = blockIdx.x * blockDim.x + threadIdx.x;
    int stride = gridDim.x * blockDim.x;
    for (; i < n; i += stride) p[i] = 0.0f;
}

__global__ void scatter_adj_kernel(const int* __restrict__ ei,
                                   const float* __restrict__ ea,
                                   float* __restrict__ adj) {
    int e = blockIdx.x * blockDim.x + threadIdx.x;
    if (e >= Ec) return;
    int u = ei[e];
    int v = ei[Ec + e];
    int b = u >> 8;
    int s = u & 255;
    int d = v & 255;
    float w = ea[e];
    atomicAdd(&adj[(b << 16) + (s << 8) + d], w);
    atomicAdd(&adj[(b << 16) + (d << 8) + s], w);
}

__global__ void encode_kernel(const float* __restrict__ x,
                              const float* __restrict__ encW,
                              const float* __restrict__ encb,
                              float* __restrict__ h) {
    int i = blockIdx.x;
    int d = threadIdx.x;
    h[i * Dc + d] = fmaf(x[i], encW[d], encb[d]);
}

// ---------------- wj stats, all layers, one tiny launch ---------------------
__global__ void wstat_kernel(const float* __restrict__ msgW,
                             float* __restrict__ wst) {
    int l = threadIdx.x >> 5, lane = threadIdx.x & 31;
    if (l >= Lc) return;
    const float* wj = msgW + (size_t)l * 257 * Dc + 2 * Dc * Dc;
    float s = 0.f, q = 0.f;
#pragma unroll
    for (int c = 0; c < 4; c++) {
        float v = wj[c * 32 + lane];
        s += v; q = fmaf(v, v, q);
    }
#pragma unroll
    for (int o = 16; o; o >>= 1) {
        s += __shfl_xor_sync(0xffffffffu, s, o);
        q += __shfl_xor_sync(0xffffffffu, q, o);
    }
    if (lane == 0) { wst[l * 2] = s * (1.0f / 128.0f); wst[l * 2 + 1] = q; }
}

// ---------------- dual GEMM, wg-split, optional fused node-stats ------------
// 256 threads: wg0 -> O1 (ht, +bias), wg1 -> O2 (hs). 8 rows/block.
template <bool STATS>
__global__ void __launch_bounds__(256) dual_mm_ns(
        const float* __restrict__ X,
        const float* __restrict__ W1,
        const float* __restrict__ W2,
        const float* __restrict__ b1,
        const float* __restrict__ wj,
        float* __restrict__ O1, float* __restrict__ O2,
        float4* __restrict__ statT, float4* __restrict__ statS) {
    __shared__ float xs[8][132];
    __shared__ float red[2][4][8][3];
    int base = blockIdx.x * 8;
    int t = threadIdx.x;
    int wg = t >> 7, tl = t & 127;
#pragma unroll
    for (int c = 0; c < 4; c++) {
        int idx = c * 256 + t;             // 0..1023
        xs[idx >> 7][idx & 127] = X[base * Dc + idx];
    }
    __syncthreads();
    const float* W = wg ? W2 : W1;
    float acc[8];
    float bv = wg ? 0.0f : b1[tl];
#pragma unroll
    for (int r = 0; r < 8; r++) acc[r] = bv;
#pragma unroll 2
    for (int k4 = 0; k4 < 32; k4++) {
        float wk[4];
#pragma unroll
        for (int kk = 0; kk < 4; kk++) wk[kk] = W[(k4 * 4 + kk) * Dc + tl];
#pragma unroll
        for (int r = 0; r < 8; r++) {
            float4 x4 = *(float4*)&xs[r][k4 * 4];
            acc[r] = fmaf(x4.x, wk[0], acc[r]);
            acc[r] = fmaf(x4.y, wk[1], acc[r]);
            acc[r] = fmaf(x4.z, wk[2], acc[r]);
            acc[r] = fmaf(x4.w, wk[3], acc[r]);
        }
    }
    float* O = wg ? O2 : O1;
#pragma unroll
    for (int r = 0; r < 8; r++) O[(base + r) * Dc + tl] = acc[r];

    if constexpr (STATS) {
        float wv = wj[tl];
        int lane = t & 31, warp = (t >> 5) & 3;
#pragma unroll
        for (int r = 0; r < 8; r++) {
            float s = acc[r], q = acc[r] * acc[r], tt = acc[r] * wv;
#pragma unroll
            for (int o = 16; o; o >>= 1) {
                s  += __shfl_xor_sync(0xffffffffu, s,  o);
                q  += __shfl_xor_sync(0xffffffffu, q,  o);
                tt += __shfl_xor_sync(0xffffffffu, tt, o);
            }
            if (lane == 0) {
                red[wg][warp][r][0] = s;
                red[wg][warp][r][1] = q;
                red[wg][warp][r][2] = tt;
            }
        }
        __syncthreads();
        if (t < 16) {
            int gi = t >> 3, r = t & 7;
            float s = 0.f, q = 0.f, tt = 0.f;
#pragma unroll
            for (int w = 0; w < 4; w++) {
                s  += red[gi][w][r][0];
                q  += red[gi][w][r][1];
                tt += red[gi][w][r][2];
            }
            float4 v = make_float4(s * (1.0f / 128.0f), q, 2.0f * tt, 0.0f);
            if (gi == 0) statT[base + r] = v; else statS[base + r] = v;
        }
    }
}

// ---------------- fused C=ht.hs + LN pair-stats -> mr -----------------------
__global__ void __launch_bounds__(256) cdot_mr_kernel(
        const float* __restrict__ ht,
        const float* __restrict__ hs,
        const float* __restrict__ adj,
        const float4* __restrict__ statT,
        const float4* __restrict__ statS,
        const float* __restrict__ wstat,
        float2* __restrict__ mr) {
    __shared__ float hts[16][132];
    __shared__ float hss[64][132];
    __shared__ float4 sTs[16];
    int base  = blockIdx.x * 16;
    int b     = base >> 8;
    int jbase = blockIdx.y * 64;
    int t = threadIdx.x;
#pragma unroll
    for (int c = 0; c < 8; c++) {
        int idx = c * 256 + t;
        hts[idx >> 7][idx & 127] = ht[base * Dc + idx];
    }
#pragma unroll
    for (int c = 0; c < 32; c++) {
        int idx = c * 256 + t;
        hss[idx >> 7][idx & 127] = hs[(b * Nc + jbase) * Dc + idx];
    }
    if (t < 16) sTs[t] = statT[base + t];
    __syncthreads();

    int jl = t & 63;
    int rg = (t >> 6) * 4;
    float acc0 = 0.f, acc1 = 0.f, acc2 = 0.f, acc3 = 0.f;
#pragma unroll 4
    for (int k4 = 0; k4 < 32; k4++) {
        float4 hv = *(float4*)&hss[jl][k4 * 4];
        float4 x0 = *(float4*)&hts[rg + 0][k4 * 4];
        float4 x1 = *(float4*)&hts[rg + 1][k4 * 4];
        float4 x2 = *(float4*)&hts[rg + 2][k4 * 4];
        float4 x3 = *(float4*)&hts[rg + 3][k4 * 4];
        acc0 = fmaf(x0.x, hv.x, acc0); acc0 = fmaf(x0.y, hv.y, acc0);
        acc0 = fmaf(x0.z, hv.z, acc0); acc0 = fmaf(x0.w, hv.w, acc0);
        acc1 = fmaf(x1.x, hv.x, acc1); acc1 = fmaf(x1.y, hv.y, acc1);
        acc1 = fmaf(x1.z, hv.z, acc1); acc1 = fmaf(x1.w, hv.w, acc1);
        acc2 = fmaf(x2.x, hv.x, acc2); acc2 = fmaf(x2.y, hv.y, acc2);
        acc2 = fmaf(x2.z, hv.z, acc2); acc2 = fmaf(x2.w, hv.w, acc2);
        acc3 = fmaf(x3.x, hv.x, acc3); acc3 = fmaf(x3.y, hv.y, acc3);
        acc3 = fmaf(x3.z, hv.z, acc3); acc3 = fmaf(x3.w, hv.w, acc3);
    }

    float4 S  = statS[b * Nc + jbase + jl];
    float Sw  = __ldg(wstat), Qw = __ldg(wstat + 1);
    float cacc[4] = {acc0, acc1, acc2, acc3};
#pragma unroll
    for (int rr = 0; rr < 4; rr++) {
        int row = base + rg + rr;
        float4 T = sTs[rg + rr];
        float a  = adj[row * Nc + jbase + jl];
        float mu   = fmaf(a, Sw, T.x + S.x);
        float sq   = fmaf(2.0f, cacc[rr], T.y + S.y);
        sq         = fmaf(a, fmaf(a, Qw, T.z + S.z), sq);
        float var  = fmaf(sq, 1.0f / 128.0f, -mu * mu);
        float r    = rsqrtf(var + 1e-5f);
        mr[row * Nc + jbase + jl] = make_float2(r, -mu * r);
    }
}

// ---------------- message: silu(LN(pre)) masked-sum over j ------------------
__global__ void __launch_bounds__(256) msg_kernel(
        const float* __restrict__ ht,
        const float* __restrict__ hs,
        const float* __restrict__ adj,
        const float* __restrict__ wjv,
        const float* __restrict__ g,
        const float* __restrict__ be,
        const float2* __restrict__ mr,
        float* __restrict__ agg) {
    int warp = threadIdx.x >> 5;
    int lane = threadIdx.x & 31;
    int b = blockIdx.x >> 5;
    int i = ((blockIdx.x & 31) << 3) + warp;
    int node = b * Nc + i;
    int d4 = lane << 2;

    const ulonglong2 HT = *(const ulonglong2*)(ht + node * Dc + d4);
    const ulonglong2 WJ = *(const ulonglong2*)(wjv + d4);
    float4 G4 = *(const float4*)(g + d4);
    float4 B4 = *(const float4*)(be + d4);
    u64 Gh01 = pk2(0.5f * G4.x, 0.5f * G4.y);
    u64 Gh23 = pk2(0.5f * G4.z, 0.5f * G4.w);
    u64 Bh01 = pk2(0.5f * B4.x, 0.5f * B4.y);
    u64 Bh23 = pk2(0.5f * B4.z, 0.5f * B4.w);

    const float* hsb = hs + b * Nc * Dc;
    const float* arow = adj + node * Nc;
    const float2* mrow = mr + node * Nc;

    u64 aP0 = 0, aP1 = 0, aT0 = 0, aT1 = 0;

#pragma unroll 2
    for (int j = 0; j < Nc; j++) {
        float a = __ldg(arow + j);
        float2 m = __ldg(mrow + j);              // {r, -mu*r}
        ulonglong2 sv = *(const ulonglong2*)(hsb + j * Dc + d4);
        u64 a2  = pk2(a, a);
        u64 r2  = pk2(m.x, m.x);
        u64 nm2 = pk2(m.y, m.y);
        u64 p0  = fma2v(a2, WJ.x, add2v(HT.x, sv.x));
        u64 p1  = fma2v(a2, WJ.y, add2v(HT.y, sv.y));
        u64 z0  = fma2v(p0, r2, nm2);
        u64 z1  = fma2v(p1, r2, nm2);
        u64 y0  = fma2v(z0, Gh01, Bh01);
        u64 y1  = fma2v(z1, Gh23, Bh23);
        float f0, f1, f2, f3;
        upk2(y0, f0, f1); upk2(y1, f2, f3);
        u64 t0 = pk2(tanh_ap(f0), tanh_ap(f1));
        u64 t1 = pk2(tanh_ap(f2), tanh_ap(f3));
        aP0 = add2v(aP0, y0);  aP1 = add2v(aP1, y1);
        aT0 = fma2v(y0, t0, aT0);
        aT1 = fma2v(y1, t1, aT1);
    }

    float ax, ay, az, aw;
    upk2(add2v(aP0, aT0), ax, ay);
    upk2(add2v(aP1, aT1), az, aw);

    // subtract diagonal j == i
    {
        float a = arow[i];
        float2 m = mrow[i];
        const float4 s = *(const float4*)(hsb + i * Dc + d4);
        float h0, h1, h2, h3, w0, w1, w2, w3, g0, g1, g2, g3, e0, e1, e2, e3;
        upk2(HT.x, h0, h1); upk2(HT.y, h2, h3);
        upk2(WJ.x, w0, w1); upk2(WJ.y, w2, w3);
        upk2(Gh01, g0, g1); upk2(Gh23, g2, g3);
        upk2(Bh01, e0, e1); upk2(Bh23, e2, e3);
        float r = m.x, nmr = m.y;
        float p, z, y2;
        p = fmaf(a, w0, h0 + s.x); z = fmaf(p, r, nmr); y2 = fmaf(z, g0, e0); ax -= fmaf(y2, tanh_ap(y2), y2);
        p = fmaf(a, w1, h1 + s.y); z = fmaf(p, r, nmr); y2 = fmaf(z, g1, e1); ay -= fmaf(y2, tanh_ap(y2), y2);
        p = fmaf(a, w2, h2 + s.z); z = fmaf(p, r, nmr); y2 = fmaf(z, g2, e2); az -= fmaf(y2, tanh_ap(y2), y2);
        p = fmaf(a, w3, h3 + s.w); z = fmaf(p, r, nmr); y2 = fmaf(z, g3, e3); aw -= fmaf(y2, tanh_ap(y2), y2);
    }
    *(float4*)(agg + node * Dc + d4) = make_float4(ax, ay, az, aw);
}

// ---------------- update: split-K across warpgroups, 8 rows/block -----------
__global__ void __launch_bounds__(256) update_kernel(
        float* __restrict__ h,
        const float* __restrict__ agg,
        const float* __restrict__ Wu,
        const float* __restrict__ bu,
        const float* __restrict__ g,
        const float* __restrict__ be) {
    __shared__ float cat[8][260];
    __shared__ float part[8][132];
    __shared__ float ubuf[8][132];
    int base = blockIdx.x * 8;
    int t = threadIdx.x;
    int wg = t >> 7, tl = t & 127;
#pragma unroll
    for (int c = 0; c < 4; c++) {
        int idx = c * 256 + t;             // 0..1023
        cat[idx >> 7][idx & 127]        = h[base * Dc + idx];
        cat[idx >> 7][Dc + (idx & 127)] = agg[base * Dc + idx];
    }
    __syncthreads();
    float acc[8];
    float bv = wg ? 0.0f : bu[tl];
#pragma unroll
    for (int r = 0; r < 8; r++) acc[r] = bv;
    const float* Wp = Wu + wg * Dc * Dc;   // wg0: k 0..127, wg1: k 128..255
    int kb = wg * Dc;
#pragma unroll 2
    for (int k4 = 0; k4 < 32; k4++) {
        float wk[4];
#pragma unroll
        for (int kk = 0; kk < 4; kk++) wk[kk] = Wp[(k4 * 4 + kk) * Dc + tl];
#pragma unroll
        for (int r = 0; r < 8; r++) {
            float4 x4 = *(float4*)&cat[r][kb + k4 * 4];
            acc[r] = fmaf(x4.x, wk[0], acc[r]);
            acc[r] = fmaf(x4.y, wk[1], acc[r]);
            acc[r] = fmaf(x4.z, wk[2], acc[r]);
            acc[r] = fmaf(x4.w, wk[3], acc[r]);
        }
    }
    if (wg == 1) {
#pragma unroll
        for (int r = 0; r < 8; r++) part[r][tl] = acc[r];
    }
    __syncthreads();
    if (wg == 0) {
#pragma unroll
        for (int r = 0; r < 8; r++) ubuf[r][tl] = acc[r] + part[r][tl];
    }
    __syncthreads();
    // LN + silu + residual: warp w handles row w (8 warps, 8 rows)
    int warp = t >> 5, lane = t & 31;
    float4 u4 = *(float4*)&ubuf[warp][lane * 4];
    float s = (u4.x + u4.y) + (u4.z + u4.w);
    float q = fmaf(u4.x, u4.x, fmaf(u4.y, u4.y, fmaf(u4.z, u4.z, u4.w * u4.w)));
#pragma unroll
    for (int o = 16; o; o >>= 1) {
        s += __shfl_xor_sync(0xffffffffu, s, o);
        q += __shfl_xor_sync(0xffffffffu, q, o);
    }
    float mu  = s * (1.0f / 128.0f);
    float var = fmaf(q, 1.0f / 128.0f, -mu * mu);
    float rv  = rsqrtf(var + 1e-5f);
    float4 g4  = *(const float4*)(g + lane * 4);
    float4 be4 = *(const float4*)(be + lane * 4);
    float4 c4  = *(float4*)&cat[warp][lane * 4];
    float4 o4;
    o4.x = c4.x + silu_f(fmaf((u4.x - mu) * rv, g4.x, be4.x));
    o4.y = c4.y + silu_f(fmaf((u4.y - mu) * rv, g4.y, be4.y));
    o4.z = c4.z + silu_f(fmaf((u4.z - mu) * rv, g4.z, be4.z));
    o4.w = c4.w + silu_f(fmaf((u4.w - mu) * rv, g4.w, be4.w));
    *(float4*)(h + (base + warp) * Dc + lane * 4) = o4;
}

// ---------------- fused decoder: e1 on the fly + 2-layer MLP ----------------
__global__ void __launch_bounds__(256) edge_kernel(
        const float* __restrict__ p, const float* __restrict__ q,
        const int* __restrict__ ei, const float* __restrict__ ea,
        const float* __restrict__ w1c,
        const float* __restrict__ W2,   // [128,64]
        const float* __restrict__ b2,
        const float* __restrict__ w3,   // [64]
        const float* __restrict__ b3,
        float* __restrict__ out) {
    __shared__ float2 W2s[Dc * 32];    // [k][lane] = {W2[k][lane], W2[k][lane+32]}
    __shared__ float w1cs[Dc];
    __shared__ float w3s[64], b2s[64];
    __shared__ float e1s[8][132];
    int t = threadIdx.x;
    for (int i = t; i < Dc * 32; i += 256) {
        int k = i >> 5, c = i & 31;
        W2s[i] = make_float2(W2[k * 64 + c], W2[k * 64 + c + 32]);
    }
    if (t < Dc) w1cs[t] = w1c[t];
    if (t < 64) { w3s[t] = w3[t]; b2s[t] = b2[t]; }
    __syncthreads();
    float b3v = b3[0];
    int warp = t >> 5, lane = t & 31;
    int gw = blockIdx.x * 8 + warp;
    int nW = gridDim.x * 8;
    for (int e = gw; e < Ec; e += nW) {
        int u = ei[e];
        int v = ei[Ec + e];
        float a = ea[e];
        float4 pv = *(const float4*)(p + u * Dc + lane * 4);
        float4 qv = *(const float4*)(q + v * Dc + lane * 4);
        float4 wc = *(const float4*)(w1cs + lane * 4);
        float4 y;
        y.x = silu_f(fmaf(a, wc.x, pv.x + qv.x));
        y.y = silu_f(fmaf(a, wc.y, pv.y + qv.y));
        y.z = silu_f(fmaf(a, wc.z, pv.z + qv.z));
        y.w = silu_f(fmaf(a, wc.w, pv.w + qv.w));
        *(float4*)&e1s[warp][lane * 4] = y;
        __syncwarp();
        float a0 = b2s[lane], a1 = b2s[lane + 32];
#pragma unroll 4
        for (int k4 = 0; k4 < 32; k4++) {
            float4 s4 = *(float4*)&e1s[warp][k4 * 4];
            float2 w0 = W2s[(k4 * 4 + 0) * 32 + lane];
            float2 w1 = W2s[(k4 * 4 + 1) * 32 + lane];
            float2 w2 = W2s[(k4 * 4 + 2) * 32 + lane];
            float2 w3v = W2s[(k4 * 4 + 3) * 32 + lane];
            a0 = fmaf(s4.x, w0.x, a0); a1 = fmaf(s4.x, w0.y, a1);
            a0 = fmaf(s4.y, w1.x, a0); a1 = fmaf(s4.y, w1.y, a1);
            a0 = fmaf(s4.z, w2.x, a0); a1 = fmaf(s4.z, w2.y, a1);
            a0 = fmaf(s4.w, w3v.x, a0); a1 = fmaf(s4.w, w3v.y, a1);
        }
        a0 = silu_f(a0);
        a1 = silu_f(a1);
        float tt = fmaf(a0, w3s[lane], a1 * w3s[lane + 32]);
#pragma unroll
        for (int o = 16; o; o >>= 1) tt += __shfl_xor_sync(0xffffffffu, tt, o);
        if (lane == 0) out[e] = tanhf(tt + b3v);
        __syncwarp();
    }
}

// ---------------- launch ----------------------------------------------------
extern "C" void kernel_launch(void* const* d_in, const int* in_sizes, int n_in,
                              void* d_out, int out_size) {
    const float* x     = (const float*)d_in[0];
    const int*   ei    = (const int*)  d_in[1];
    const float* ea    = (const float*)d_in[2];
    const float* encW  = (const float*)d_in[4];
    const float* encb  = (const float*)d_in[5];
    const float* msgW  = (const float*)d_in[6];
    const float* msgb  = (const float*)d_in[7];
    const float* msgg  = (const float*)d_in[8];
    const float* msgbe = (const float*)d_in[9];
    const float* updW  = (const float*)d_in[10];
    const float* updb  = (const float*)d_in[11];
    const float* updg  = (const float*)d_in[12];
    const float* updbe = (const float*)d_in[13];
    const float* decW1 = (const float*)d_in[14];
    const float* decb1 = (const float*)d_in[15];
    const float* decW2 = (const float*)d_in[16];
    const float* decb2 = (const float*)d_in[17];
    const float* decW3 = (const float*)d_in[18];
    const float* decb3 = (const float*)d_in[19];
    float* out = (float*)d_out;

    float *adj, *h, *ht, *hs, *agg, *p, *q, *wst;
    float2* mr; float4 *sT, *sS;
    cudaGetSymbolAddress((void**)&adj, g_adj);
    cudaGetSymbolAddress((void**)&h,   g_h);
    cudaGetSymbolAddress((void**)&ht,  g_ht);
    cudaGetSymbolAddress((void**)&hs,  g_hs);
    cudaGetSymbolAddress((void**)&agg, g_agg);
    cudaGetSymbolAddress((void**)&p,   g_p);
    cudaGetSymbolAddress((void**)&q,   g_q);
    cudaGetSymbolAddress((void**)&mr,  g_mr);
    cudaGetSymbolAddress((void**)&sT,  g_statT);
    cudaGetSymbolAddress((void**)&sS,  g_statS);
    cudaGetSymbolAddress((void**)&wst, g_wstat);

    zero_kernel<<<1024, 256>>>(adj, ADJ_ELEMS);
    scatter_adj_kernel<<<(Ec + 255) / 256, 256>>>(ei, ea, adj);
    encode_kernel<<<BN, Dc>>>(x, encW, encb, h);
    wstat_kernel<<<1, 32 * Lc>>>(msgW, wst);

    for (int l = 0; l < Lc; l++) {
        const float* Wl  = msgW + (size_t)l * 257 * Dc;
        const float* wjv = Wl + 2 * Dc * Dc;
        dual_mm_ns<true><<<BN / 8, 256>>>(h, Wl, Wl + Dc * Dc, msgb + l * Dc,
                                          wjv, ht, hs, sT, sS);
        cdot_mr_kernel<<<dim3(BN / 16, Nc / 64), 256>>>(ht, hs, adj, sT, sS,
                                                        wst + 2 * l, mr);
        msg_kernel<<<Bc * 32, 256>>>(ht, hs, adj, wjv,
                                     msgg + l * Dc, msgbe + l * Dc, mr, agg);
        update_kernel<<<BN / 8, 256>>>(h, agg, updW + (size_t)l * 2 * Dc * Dc,
                                       updb + l * Dc, updg + l * Dc, updbe + l * Dc);
    }

    dual_mm_ns<false><<<BN / 8, 256>>>(h, decW1, decW1 + Dc * Dc, decb1,
                                       nullptr, p, q, nullptr, nullptr);
    edge_kernel<<<512, 256>>>(p, q, ei, ea, decW1 + 2 * Dc * Dc,
                              decW2, decb2, decW3, decb3, out);
}